// round 15
// baseline (speedup 1.0000x reference)
#include <cuda_runtime.h>
#include <cuda_fp16.h>
#include <math.h>
#include <cstdint>

// Problem constants
#define BATCH   4
#define SEQ     8192
#define DMODEL  1024
#define NHEADS  16
#define HEADDIM 64
#define CHUNK   256
#define NBLKS   (SEQ / CHUNK)        // 32
#define MROWS   (BATCH * SEQ)        // 32768

// ---------------------------------------------------------------------------
// Scratch (device globals — no runtime allocation allowed)
// ---------------------------------------------------------------------------
__device__ __half g_Qh[(size_t)MROWS * DMODEL];      // Q fp16 (pre-scaled by log2e/32)
__device__ __half g_Kh[(size_t)MROWS * DMODEL];      // K fp16
__device__ __half g_Vh[(size_t)MROWS * DMODEL];      // V fp16
__device__ __half g_Ch[(size_t)MROWS * DMODEL];      // ctx fp16
__device__ __half g_Wt[4][(size_t)DMODEL * DMODEL];  // W^T fp16 (K-major)

// ---------------------------------------------------------------------------
// PTX helpers (baseline sm_80 features only)
// ---------------------------------------------------------------------------
__device__ __forceinline__ uint32_t smem_u32(const void* p) {
    uint32_t a;
    asm("{ .reg .u64 t; cvta.to.shared.u64 t, %1; cvt.u32.u64 %0, t; }"
        : "=r"(a) : "l"(p));
    return a;
}
#define CP_ASYNC16(dst, src) \
    asm volatile("cp.async.cg.shared.global [%0], [%1], 16;" \
                 :: "r"(dst), "l"(src))
#define CP_COMMIT() asm volatile("cp.async.commit_group;" ::: "memory")
#define CP_WAIT(n)  asm volatile("cp.async.wait_group %0;" :: "n"(n) : "memory")

__device__ __forceinline__ void mma16816(float* c, const uint32_t* a, const uint32_t* b) {
    asm volatile(
        "mma.sync.aligned.m16n8k16.row.col.f32.f16.f16.f32 "
        "{%0,%1,%2,%3}, {%4,%5,%6,%7}, {%8,%9}, {%0,%1,%2,%3};"
        : "+f"(c[0]), "+f"(c[1]), "+f"(c[2]), "+f"(c[3])
        : "r"(a[0]), "r"(a[1]), "r"(a[2]), "r"(a[3]), "r"(b[0]), "r"(b[1]));
}
__device__ __forceinline__ void ldm_x4(uint32_t* r, uint32_t addr) {
    asm volatile("ldmatrix.sync.aligned.m8n8.x4.shared.b16 {%0,%1,%2,%3}, [%4];"
                 : "=r"(r[0]), "=r"(r[1]), "=r"(r[2]), "=r"(r[3]) : "r"(addr));
}
__device__ __forceinline__ void ldm_x4_t(uint32_t* r, uint32_t addr) {
    asm volatile("ldmatrix.sync.aligned.m8n8.x4.trans.shared.b16 {%0,%1,%2,%3}, [%4];"
                 : "=r"(r[0]), "=r"(r[1]), "=r"(r[2]), "=r"(r[3]) : "r"(addr));
}
__device__ __forceinline__ uint32_t packh2(float a, float b) {
    __half2 h = __floats2half2_rn(a, b);
    return *(uint32_t*)&h;
}
__device__ __forceinline__ uint32_t ex2h2(uint32_t a) {
    uint32_t d;
    asm("ex2.approx.f16x2 %0, %1;" : "=r"(d) : "r"(a));
    return d;
}

// ---------------------------------------------------------------------------
// Fused weight transpose+convert (4 weights, one launch)
// ---------------------------------------------------------------------------
__global__ __launch_bounds__(256)
void wconv4(const float* __restrict__ W0, const float* __restrict__ W1,
            const float* __restrict__ W2, const float* __restrict__ W3,
            __half* __restrict__ T)
{
    __shared__ float t[32][33];
    const int z = blockIdx.z;
    const float* W = (z == 0) ? W0 : (z == 1) ? W1 : (z == 2) ? W2 : W3;
    __half* To = T + (size_t)z * DMODEL * DMODEL;
    const int n0 = blockIdx.x * 32, k0 = blockIdx.y * 32;
    const int tx = threadIdx.x & 31, ty = threadIdx.x >> 5;
    #pragma unroll
    for (int i = 0; i < 4; i++) {
        int k = k0 + ty + i * 8;
        t[ty + i * 8][tx] = W[(size_t)k * DMODEL + n0 + tx];
    }
    __syncthreads();
    #pragma unroll
    for (int i = 0; i < 4; i++) {
        int n = n0 + ty + i * 8;
        To[(size_t)n * DMODEL + k0 + tx] = __float2half(t[tx][ty + i * 8]);
    }
}

// ---------------------------------------------------------------------------
// GEMM geometry: CTA 128x256, BK=64 (R13 sweet spot), 512 thr / 16 warps,
// warp tile 64x32, fp32 accum, NPIPE=3 cp.async with CP_WAIT(1) — each
// B stage has 2 MMA-stage windows of slack. Race-free: all writes to slot
// (c+2)%3 follow the top-of-loop sync that retires mma(c-1)'s readers.
// 72-half padded rows (144B stride, conflict-free ldmatrix).
// ---------------------------------------------------------------------------
#define NTHR 512
#define BM 128
#define BN 256
#define BK 64
#define SA 72
#define TILE_A  (BM * SA * 2)        // 18432
#define TILE_BB (BN * SA * 2)        // 36864
#define OFF_B   TILE_A
#define STAGE_B (TILE_A + TILE_BB)   // 55296
#define NPIPE 3
#define GEMM_SMEM (NPIPE * STAGE_B)  // 165888
#define NSTAGE (DMODEL / BK)         // 16
#define QSCALE 0.04508422f           // log2(e)/32

// B stage: 256 rows x 8 chunks(16B) = 2048 ops / 512 = 4 iters
__device__ __forceinline__ void load_B(
    uint32_t sbase, int slot, int tid,
    const __half* __restrict__ B, int n0, int k0)
{
    const uint32_t st = sbase + slot * STAGE_B + OFF_B;
    #pragma unroll
    for (int it = 0; it < 4; it++) {
        int u = tid + it * NTHR;
        int row = u >> 3, ch = u & 7;
        CP_ASYNC16(st + (uint32_t)(row * SA * 2 + ch * 16),
                   B + (size_t)(n0 + row) * DMODEL + k0 + ch * 8);
    }
    CP_COMMIT();
}
// A+B stage (fp16 A path, gemm_o): A 2 iters, B 4 iters
__device__ __forceinline__ void load_AB(
    uint32_t sbase, int slot, int tid,
    const __half* __restrict__ A, const __half* __restrict__ B,
    int r0, int n0, int k0)
{
    const uint32_t st = sbase + slot * STAGE_B;
    #pragma unroll
    for (int it = 0; it < 2; it++) {
        int u = tid + it * NTHR;
        int row = u >> 3, ch = u & 7;
        CP_ASYNC16(st + (uint32_t)(row * SA * 2 + ch * 16),
                   A + (size_t)(r0 + row) * DMODEL + k0 + ch * 8);
    }
    #pragma unroll
    for (int it = 0; it < 4; it++) {
        int u = tid + it * NTHR;
        int row = u >> 3, ch = u & 7;
        CP_ASYNC16(st + OFF_B + (uint32_t)(row * SA * 2 + ch * 16),
                   B + (size_t)(n0 + row) * DMODEL + k0 + ch * 8);
    }
    CP_COMMIT();
}
// fp32 A stage (qkv): 128 rows x 16 float4 = 2048 / 512 = 4 per thread
__device__ __forceinline__ void ldgA(float4* r, const float* __restrict__ X,
                                     int r0, int k0, int tid)
{
    #pragma unroll
    for (int it = 0; it < 4; it++) {
        int u = tid + it * NTHR;
        int row = u >> 4, ch = u & 15;
        r[it] = *(const float4*)&X[(size_t)(r0 + row) * DMODEL + k0 + ch * 4];
    }
}
__device__ __forceinline__ void stsA(char* smem, int slot, const float4* r, int tid)
{
    char* st = smem + slot * STAGE_B;
    #pragma unroll
    for (int it = 0; it < 4; it++) {
        int u = tid + it * NTHR;
        int row = u >> 4, ch = u & 15;
        uint2 v;
        v.x = packh2(r[it].x, r[it].y);
        v.y = packh2(r[it].z, r[it].w);
        *(uint2*)(st + row * (SA * 2) + ch * 8) = v;
    }
}

#define GEMM_LANE_SETUP() \
    const int tid  = threadIdx.x; \
    const int wid  = tid >> 5; \
    const int lane = tid & 31; \
    const int wm = wid & 1; \
    const int wn = wid >> 1; \
    const int g  = lane >> 2; \
    const int tq = lane & 3; \
    const int quad = lane >> 3; \
    const int qr   = lane & 7; \
    const uint32_t a_off = (uint32_t)((wm * 64 + (quad & 1) * 8 + qr) * SA * 2 \
                                      + (quad >> 1) * 16); \
    const uint32_t b_off = (uint32_t)OFF_B \
                         + (uint32_t)((wn * 32 + (quad >> 1) * 8 + qr) * SA * 2 \
                                      + (quad & 1) * 16)

__device__ __forceinline__ void mma_stage(uint32_t st, uint32_t a_off, uint32_t b_off,
                                          float acc[4][4][4])
{
    #pragma unroll
    for (int kk = 0; kk < BK; kk += 16) {
        uint32_t af[4][4], bf[8];
        #pragma unroll
        for (int mt = 0; mt < 4; mt++)
            ldm_x4(af[mt], st + a_off + (uint32_t)(mt * 16 * SA * 2 + kk * 2));
        #pragma unroll
        for (int p = 0; p < 2; p++)
            ldm_x4(&bf[p * 4], st + b_off + (uint32_t)(p * 16 * SA * 2 + kk * 2));
        #pragma unroll
        for (int mt = 0; mt < 4; mt++)
            #pragma unroll
            for (int nt = 0; nt < 4; nt++)
                mma16816(acc[mt][nt], af[mt], &bf[nt * 2]);
    }
}

// slot index mod 3
__device__ __forceinline__ int s3(int c) { int m = c % 3; return m; }

// ---------------------------------------------------------------------------
// Fused QKV GEMM: A = x fp32 converted in-kernel.
// Per iter c: CP_WAIT(1) [stage c's B done, c+1 may fly] -> sync ->
//   issue B(c+2) -> LDG A(c+1) -> MMA(c) -> STS A(c+1).
// ---------------------------------------------------------------------------
__global__ __launch_bounds__(NTHR, 1)
void gemm_qkv(const float* __restrict__ X, const __half* __restrict__ Wt,
              const float* __restrict__ bq, const float* __restrict__ bk,
              const float* __restrict__ bv,
              __half* __restrict__ Qo, __half* __restrict__ Ko,
              __half* __restrict__ Vo)
{
    extern __shared__ char smem[];
    const uint32_t sbase = smem_u32(smem);
    GEMM_LANE_SETUP();

    const int wsel = blockIdx.x >> 2;
    const int n0   = (blockIdx.x & 3) * BN;
    const int r0   = blockIdx.y * BM;
    const __half* B = Wt + (size_t)wsel * DMODEL * DMODEL;
    const float* bias = (wsel == 0) ? bq : (wsel == 1) ? bk : bv;
    __half* C = (wsel == 0) ? Qo : (wsel == 1) ? Ko : Vo;
    const float osc = (wsel == 0) ? QSCALE : 1.0f;

    float acc[4][4][4];
    #pragma unroll
    for (int i = 0; i < 4; i++)
        #pragma unroll
        for (int j = 0; j < 4; j++)
            #pragma unroll
            for (int r = 0; r < 4; r++) acc[i][j][r] = 0.0f;

    // prologue: B stages 0,1 async; A stage 0 ldg+sts
    load_B(sbase, 0, tid, B, n0, 0);
    load_B(sbase, 1, tid, B, n0, BK);
    {
        float4 ar[4];
        ldgA(ar, X, r0, 0, tid);
        stsA(smem, 0, ar, tid);
    }

    for (int c = 0; c < NSTAGE; c++) {
        if (c + 1 < NSTAGE) { CP_WAIT(1); } else { CP_WAIT(0); }
        __syncthreads();                       // retires mma(c-1) readers
        if (c + 2 < NSTAGE)
            load_B(sbase, s3(c + 2), tid, B, n0, (c + 2) * BK);

        float4 ar[4];
        if (c + 1 < NSTAGE) ldgA(ar, X, r0, (c + 1) * BK, tid);

        mma_stage(sbase + s3(c) * STAGE_B, a_off, b_off, acc);

        if (c + 1 < NSTAGE) stsA(smem, s3(c + 1), ar, tid);
    }

    #pragma unroll
    for (int mt = 0; mt < 4; mt++) {
        int row0 = r0 + wm * 64 + mt * 16 + g;
        #pragma unroll
        for (int nt = 0; nt < 4; nt++) {
            int col = n0 + wn * 32 + nt * 8 + tq * 2;
            float2 bvv = *(const float2*)&bias[col];
            *(uint32_t*)&C[(size_t)row0 * DMODEL + col] =
                packh2((acc[mt][nt][0] + bvv.x) * osc, (acc[mt][nt][1] + bvv.y) * osc);
            *(uint32_t*)&C[(size_t)(row0 + 8) * DMODEL + col] =
                packh2((acc[mt][nt][2] + bvv.x) * osc, (acc[mt][nt][3] + bvv.y) * osc);
        }
    }
}

// ---------------------------------------------------------------------------
// O-projection GEMM (fp32 accum, fp16 A via cp.async); NPIPE=3, CP_WAIT(1).
// ---------------------------------------------------------------------------
__global__ __launch_bounds__(NTHR, 1)
void gemm_o(const __half* __restrict__ A, const __half* __restrict__ B,
            const float* __restrict__ bias, float* __restrict__ C)
{
    extern __shared__ char smem[];
    const uint32_t sbase = smem_u32(smem);
    GEMM_LANE_SETUP();

    const int r0 = blockIdx.y * BM;
    const int n0 = blockIdx.x * BN;

    float acc[4][4][4];
    #pragma unroll
    for (int i = 0; i < 4; i++)
        #pragma unroll
        for (int j = 0; j < 4; j++)
            #pragma unroll
            for (int r = 0; r < 4; r++) acc[i][j][r] = 0.0f;

    load_AB(sbase, 0, tid, A, B, r0, n0, 0);
    load_AB(sbase, 1, tid, A, B, r0, n0, BK);

    for (int c = 0; c < NSTAGE; c++) {
        if (c + 1 < NSTAGE) { CP_WAIT(1); } else { CP_WAIT(0); }
        __syncthreads();
        if (c + 2 < NSTAGE)
            load_AB(sbase, s3(c + 2), tid, A, B, r0, n0, (c + 2) * BK);
        mma_stage(sbase + s3(c) * STAGE_B, a_off, b_off, acc);
    }

    #pragma unroll
    for (int mt = 0; mt < 4; mt++) {
        int row0 = r0 + wm * 64 + mt * 16 + g;
        #pragma unroll
        for (int nt = 0; nt < 4; nt++) {
            int col = n0 + wn * 32 + nt * 8 + tq * 2;
            float2 bvv = *(const float2*)&bias[col];
            *(float2*)&C[(size_t)row0 * DMODEL + col] =
                make_float2(acc[mt][nt][0] + bvv.x, acc[mt][nt][1] + bvv.y);
            *(float2*)&C[(size_t)(row0 + 8) * DMODEL + col] =
                make_float2(acc[mt][nt][2] + bvv.x, acc[mt][nt][3] + bvv.y);
        }
    }
}

// ---------------------------------------------------------------------------
// Tensor-core block-diagonal attention (unchanged from R13)
// ---------------------------------------------------------------------------
#define ASW(o) ((o) ^ (((o) >> 3) & 0x70))
#define AKV_B  (CHUNK * 128)
#define ATTN_SMEM (2 * AKV_B)          // 65536

__global__ __launch_bounds__(128, 3)
void attn_tc(const __half* __restrict__ Qg, const __half* __restrict__ Kg,
             const __half* __restrict__ Vg, __half* __restrict__ ctx)
{
    extern __shared__ char smc[];
    const uint32_t sbK = smem_u32(smc);
    const uint32_t sbV = sbK + AKV_B;

    const int gb = blockIdx.x >> 1, qh = blockIdx.x & 1;
    const int h = blockIdx.y, b = blockIdx.z;
    const int tid = threadIdx.x;
    const int rowBase  = b * SEQ + gb * CHUNK;
    const int qRowBase = rowBase + qh * 128;
    const int colBase  = h * HEADDIM;

    #pragma unroll
    for (int it = 0; it < 16; it++) {
        int u = tid + it * 128;
        int r = u >> 3, ch = u & 7;
        uint32_t so = ASW((uint32_t)(r * 128 + ch * 16));
        size_t go = (size_t)(rowBase + r) * DMODEL + colBase + ch * 8;
        CP_ASYNC16(sbK + so, Kg + go);
        CP_ASYNC16(sbV + so, Vg + go);
    }
    CP_COMMIT();

    const int wid  = tid >> 5;
    const int lane = tid & 31;
    const int g  = lane >> 2;
    const int tq = lane & 3;
    const int quad = lane >> 3;
    const int qr   = lane & 7;
    const int qrow0 = wid * 32;

    uint32_t qf[2][4][4];
    {
        const __half* Qp = Qg + (size_t)(qRowBase + qrow0) * DMODEL + colBase;
        #pragma unroll
        for (int mt = 0; mt < 2; mt++)
            #pragma unroll
            for (int ks = 0; ks < 4; ks++) {
                size_t base = (size_t)(mt * 16 + g) * DMODEL + ks * 16 + tq * 2;
                qf[mt][ks][0] = *(const uint32_t*)&Qp[base];
                qf[mt][ks][1] = *(const uint32_t*)&Qp[base + 8 * DMODEL];
                qf[mt][ks][2] = *(const uint32_t*)&Qp[base + 8];
                qf[mt][ks][3] = *(const uint32_t*)&Qp[base + 8 * DMODEL + 8];
            }
    }

    float o[2][8][4];
    float ol[2][4];
    #pragma unroll
    for (int mt = 0; mt < 2; mt++) {
        #pragma unroll
        for (int nt = 0; nt < 8; nt++)
            #pragma unroll
            for (int r = 0; r < 4; r++) o[mt][nt][r] = 0.0f;
        #pragma unroll
        for (int r = 0; r < 4; r++) ol[mt][r] = 0.0f;
    }
    const uint32_t onesf[2] = {0x3C003C00u, 0x3C003C00u};

    CP_WAIT(0);
    __syncthreads();

    for (int kt = 0; kt < 4; kt++) {
        float s[2][8][4];
        #pragma unroll
        for (int mt = 0; mt < 2; mt++)
            #pragma unroll
            for (int nt = 0; nt < 8; nt++)
                #pragma unroll
                for (int r = 0; r < 4; r++) s[mt][nt][r] = 0.0f;

        #pragma unroll
        for (int ks = 0; ks < 4; ks++) {
            #pragma unroll
            for (int np = 0; np < 4; np++) {
                uint32_t kf[4];
                uint32_t addr = sbK + ASW((uint32_t)(
                    (kt * 64 + np * 16 + (quad >> 1) * 8 + qr) * 128
                    + (quad & 1) * 16 + ks * 32));
                ldm_x4(kf, addr);
                #pragma unroll
                for (int mt = 0; mt < 2; mt++) {
                    mma16816(s[mt][2 * np],     qf[mt][ks], &kf[0]);
                    mma16816(s[mt][2 * np + 1], qf[mt][ks], &kf[2]);
                }
            }
        }

        uint32_t pf[2][4][4];
        #pragma unroll
        for (int mt = 0; mt < 2; mt++)
            #pragma unroll
            for (int ks = 0; ks < 4; ks++) {
                pf[mt][ks][0] = ex2h2(packh2(s[mt][2 * ks][0],     s[mt][2 * ks][1]));
                pf[mt][ks][1] = ex2h2(packh2(s[mt][2 * ks][2],     s[mt][2 * ks][3]));
                pf[mt][ks][2] = ex2h2(packh2(s[mt][2 * ks + 1][0], s[mt][2 * ks + 1][1]));
                pf[mt][ks][3] = ex2h2(packh2(s[mt][2 * ks + 1][2], s[mt][2 * ks + 1][3]));
            }

        #pragma unroll
        for (int ks = 0; ks < 4; ks++) {
            #pragma unroll
            for (int np = 0; np < 4; np++) {
                uint32_t vf[4];
                uint32_t addr = sbV + ASW((uint32_t)(
                    (kt * 64 + ks * 16 + (quad & 1) * 8 + qr) * 128
                    + np * 32 + (quad >> 1) * 16));
                ldm_x4_t(vf, addr);
                #pragma unroll
                for (int mt = 0; mt < 2; mt++) {
                    mma16816(o[mt][2 * np],     pf[mt][ks], &vf[0]);
                    mma16816(o[mt][2 * np + 1], pf[mt][ks], &vf[2]);
                }
            }
            #pragma unroll
            for (int mt = 0; mt < 2; mt++)
                mma16816(ol[mt], pf[mt][ks], onesf);
        }
    }

    #pragma unroll
    for (int mt = 0; mt < 2; mt++) {
        #pragma unroll
        for (int h2 = 0; h2 < 2; h2++) {
            float inv = 1.0f / ol[mt][2 * h2];
            int row = qRowBase + qrow0 + mt * 16 + h2 * 8 + g;
            #pragma unroll
            for (int nt = 0; nt < 8; nt++) {
                uint32_t v = packh2(o[mt][nt][2 * h2] * inv, o[mt][nt][2 * h2 + 1] * inv);
                *(uint32_t*)&ctx[(size_t)row * DMODEL + colBase + nt * 8 + tq * 2] = v;
            }
        }
    }
}

// ---------------------------------------------------------------------------
// Launch — 4 kernels total
// ---------------------------------------------------------------------------
extern "C" void kernel_launch(void* const* d_in, const int* in_sizes, int n_in,
                              void* d_out, int out_size)
{
    const float* x  = (const float*)d_in[0];
    const float* Wq = (const float*)d_in[1];
    const float* bq = (const float*)d_in[2];
    const float* Wk = (const float*)d_in[3];
    const float* bk = (const float*)d_in[4];
    const float* Wv = (const float*)d_in[5];
    const float* bv = (const float*)d_in[6];
    const float* Wo = (const float*)d_in[7];
    const float* bo = (const float*)d_in[8];
    float* out = (float*)d_out;

    __half *Qh, *Kh, *Vh, *Ch, *Wt;
    cudaGetSymbolAddress((void**)&Qh, g_Qh);
    cudaGetSymbolAddress((void**)&Kh, g_Kh);
    cudaGetSymbolAddress((void**)&Vh, g_Vh);
    cudaGetSymbolAddress((void**)&Ch, g_Ch);
    cudaGetSymbolAddress((void**)&Wt, g_Wt);
    const size_t WSZ = (size_t)DMODEL * DMODEL;

    cudaFuncSetAttribute(gemm_qkv,
                         cudaFuncAttributeMaxDynamicSharedMemorySize, GEMM_SMEM);
    cudaFuncSetAttribute(gemm_o,
                         cudaFuncAttributeMaxDynamicSharedMemorySize, GEMM_SMEM);
    cudaFuncSetAttribute(attn_tc,
                         cudaFuncAttributeMaxDynamicSharedMemorySize, ATTN_SMEM);

    wconv4<<<dim3(DMODEL / 32, DMODEL / 32, 4), 256>>>(Wq, Wk, Wv, Wo, Wt);

    gemm_qkv<<<dim3(12, MROWS / BM), NTHR, GEMM_SMEM>>>(
        x, Wt, bq, bk, bv, Qh, Kh, Vh);

    attn_tc<<<dim3(NBLKS * 2, NHEADS, BATCH), 128, ATTN_SMEM>>>(Qh, Kh, Vh, Ch);

    gemm_o<<<dim3(DMODEL / BN, MROWS / BM), NTHR, GEMM_SMEM>>>(
        Ch, Wt + 3 * WSZ, bo, out);
}

// round 16
// speedup vs baseline: 1.1039x; 1.1039x over previous
#include <cuda_runtime.h>
#include <cuda_fp16.h>
#include <math.h>
#include <cstdint>

// Problem constants
#define BATCH   4
#define SEQ     8192
#define DMODEL  1024
#define NHEADS  16
#define HEADDIM 64
#define CHUNK   256
#define NBLKS   (SEQ / CHUNK)        // 32
#define MROWS   (BATCH * SEQ)        // 32768

// ---------------------------------------------------------------------------
// Scratch (device globals — no runtime allocation allowed)
// ---------------------------------------------------------------------------
__device__ __half g_Qh[(size_t)MROWS * DMODEL];      // Q fp16 (pre-scaled by log2e/32)
__device__ __half g_Kh[(size_t)MROWS * DMODEL];      // K fp16
__device__ __half g_Vh[(size_t)MROWS * DMODEL];      // V fp16
__device__ __half g_Ch[(size_t)MROWS * DMODEL];      // ctx fp16
__device__ __half g_Wt[4][(size_t)DMODEL * DMODEL];  // W^T fp16 (K-major)

// ---------------------------------------------------------------------------
// PTX helpers (baseline sm_80 features only)
// ---------------------------------------------------------------------------
__device__ __forceinline__ uint32_t smem_u32(const void* p) {
    uint32_t a;
    asm("{ .reg .u64 t; cvta.to.shared.u64 t, %1; cvt.u32.u64 %0, t; }"
        : "=r"(a) : "l"(p));
    return a;
}
#define CP_ASYNC16(dst, src) \
    asm volatile("cp.async.cg.shared.global [%0], [%1], 16;" \
                 :: "r"(dst), "l"(src))
#define CP_COMMIT() asm volatile("cp.async.commit_group;" ::: "memory")
#define CP_WAIT(n)  asm volatile("cp.async.wait_group %0;" :: "n"(n) : "memory")

__device__ __forceinline__ void mma16816(float* c, const uint32_t* a, const uint32_t* b) {
    asm volatile(
        "mma.sync.aligned.m16n8k16.row.col.f32.f16.f16.f32 "
        "{%0,%1,%2,%3}, {%4,%5,%6,%7}, {%8,%9}, {%0,%1,%2,%3};"
        : "+f"(c[0]), "+f"(c[1]), "+f"(c[2]), "+f"(c[3])
        : "r"(a[0]), "r"(a[1]), "r"(a[2]), "r"(a[3]), "r"(b[0]), "r"(b[1]));
}
__device__ __forceinline__ void ldm_x4(uint32_t* r, uint32_t addr) {
    asm volatile("ldmatrix.sync.aligned.m8n8.x4.shared.b16 {%0,%1,%2,%3}, [%4];"
                 : "=r"(r[0]), "=r"(r[1]), "=r"(r[2]), "=r"(r[3]) : "r"(addr));
}
__device__ __forceinline__ void ldm_x4_t(uint32_t* r, uint32_t addr) {
    asm volatile("ldmatrix.sync.aligned.m8n8.x4.trans.shared.b16 {%0,%1,%2,%3}, [%4];"
                 : "=r"(r[0]), "=r"(r[1]), "=r"(r[2]), "=r"(r[3]) : "r"(addr));
}
__device__ __forceinline__ uint32_t packh2(float a, float b) {
    __half2 h = __floats2half2_rn(a, b);
    return *(uint32_t*)&h;
}
__device__ __forceinline__ uint32_t ex2h2(uint32_t a) {
    uint32_t d;
    asm("ex2.approx.f16x2 %0, %1;" : "=r"(d) : "r"(a));
    return d;
}

// ---------------------------------------------------------------------------
// Fused weight transpose+convert (4 weights, one launch)
// ---------------------------------------------------------------------------
__global__ __launch_bounds__(256)
void wconv4(const float* __restrict__ W0, const float* __restrict__ W1,
            const float* __restrict__ W2, const float* __restrict__ W3,
            __half* __restrict__ T)
{
    __shared__ float t[32][33];
    const int z = blockIdx.z;
    const float* W = (z == 0) ? W0 : (z == 1) ? W1 : (z == 2) ? W2 : W3;
    __half* To = T + (size_t)z * DMODEL * DMODEL;
    const int n0 = blockIdx.x * 32, k0 = blockIdx.y * 32;
    const int tx = threadIdx.x & 31, ty = threadIdx.x >> 5;
    #pragma unroll
    for (int i = 0; i < 4; i++) {
        int k = k0 + ty + i * 8;
        t[ty + i * 8][tx] = W[(size_t)k * DMODEL + n0 + tx];
    }
    __syncthreads();
    #pragma unroll
    for (int i = 0; i < 4; i++) {
        int n = n0 + ty + i * 8;
        To[(size_t)n * DMODEL + k0 + tx] = __float2half(t[tx][ty + i * 8]);
    }
}

// ---------------------------------------------------------------------------
// GEMM geometry: CTA 128x128, BK=64, 256 thr / 8 warps (2x4),
// warp tile 64x32, fp32 accum, NPIPE=2 (R13's race-free order).
// smem 72KB/CTA -> 2 CTAs per SM: two INDEPENDENT barrier domains so one
// CTA's sync/loader bubble is covered by the other's MMA stream.
// 72-half padded rows (144B stride, conflict-free ldmatrix).
// ---------------------------------------------------------------------------
#define NTHR 256
#define BM 128
#define BN 128
#define BK 64
#define SA 72
#define TILE_A  (BM * SA * 2)        // 18432
#define TILE_BB (BN * SA * 2)        // 18432
#define OFF_B   TILE_A
#define STAGE_B (TILE_A + TILE_BB)   // 36864
#define NPIPE 2
#define GEMM_SMEM (NPIPE * STAGE_B)  // 73728
#define NSTAGE (DMODEL / BK)         // 16
#define QSCALE 0.04508422f           // log2(e)/32

// B stage: 128 rows x 8 chunks(16B) = 1024 ops / 256 = 4 iters
__device__ __forceinline__ void load_B(
    uint32_t sbase, int slot, int tid,
    const __half* __restrict__ B, int n0, int k0)
{
    const uint32_t st = sbase + slot * STAGE_B + OFF_B;
    #pragma unroll
    for (int it = 0; it < 4; it++) {
        int u = tid + it * NTHR;
        int row = u >> 3, ch = u & 7;
        CP_ASYNC16(st + (uint32_t)(row * SA * 2 + ch * 16),
                   B + (size_t)(n0 + row) * DMODEL + k0 + ch * 8);
    }
    CP_COMMIT();
}
// A+B stage (fp16 A path, gemm_o): A 4 iters + B 4 iters
__device__ __forceinline__ void load_AB(
    uint32_t sbase, int slot, int tid,
    const __half* __restrict__ A, const __half* __restrict__ B,
    int r0, int n0, int k0)
{
    const uint32_t st = sbase + slot * STAGE_B;
    #pragma unroll
    for (int it = 0; it < 4; it++) {
        int u = tid + it * NTHR;
        int row = u >> 3, ch = u & 7;
        CP_ASYNC16(st + (uint32_t)(row * SA * 2 + ch * 16),
                   A + (size_t)(r0 + row) * DMODEL + k0 + ch * 8);
    }
    #pragma unroll
    for (int it = 0; it < 4; it++) {
        int u = tid + it * NTHR;
        int row = u >> 3, ch = u & 7;
        CP_ASYNC16(st + OFF_B + (uint32_t)(row * SA * 2 + ch * 16),
                   B + (size_t)(n0 + row) * DMODEL + k0 + ch * 8);
    }
    CP_COMMIT();
}
// fp32 A half-stage (qkv): stage = 128 rows x 16 float4 = 2048 ops;
// half = 1024 ops / 256 thr = 4 per thread (16 transient regs).
__device__ __forceinline__ void ldgA_half(float4* r, const float* __restrict__ X,
                                          int r0, int k0, int tid, int half)
{
    #pragma unroll
    for (int it = 0; it < 4; it++) {
        int u = tid + (half * 4 + it) * NTHR;
        int row = u >> 4, ch = u & 15;
        r[it] = *(const float4*)&X[(size_t)(r0 + row) * DMODEL + k0 + ch * 4];
    }
}
__device__ __forceinline__ void stsA_half(char* smem, int slot, const float4* r,
                                          int tid, int half)
{
    char* st = smem + slot * STAGE_B;
    #pragma unroll
    for (int it = 0; it < 4; it++) {
        int u = tid + (half * 4 + it) * NTHR;
        int row = u >> 4, ch = u & 15;
        uint2 v;
        v.x = packh2(r[it].x, r[it].y);
        v.y = packh2(r[it].z, r[it].w);
        *(uint2*)(st + row * (SA * 2) + ch * 8) = v;
    }
}

#define GEMM_LANE_SETUP() \
    const int tid  = threadIdx.x; \
    const int wid  = tid >> 5; \
    const int lane = tid & 31; \
    const int wm = wid & 1; \
    const int wn = wid >> 1; \
    const int g  = lane >> 2; \
    const int tq = lane & 3; \
    const int quad = lane >> 3; \
    const int qr   = lane & 7; \
    const uint32_t a_off = (uint32_t)((wm * 64 + (quad & 1) * 8 + qr) * SA * 2 \
                                      + (quad >> 1) * 16); \
    const uint32_t b_off = (uint32_t)OFF_B \
                         + (uint32_t)((wn * 32 + (quad >> 1) * 8 + qr) * SA * 2 \
                                      + (quad & 1) * 16)

__device__ __forceinline__ void mma_stage(uint32_t st, uint32_t a_off, uint32_t b_off,
                                          float acc[4][4][4])
{
    #pragma unroll
    for (int kk = 0; kk < BK; kk += 16) {
        uint32_t af[4][4], bf[8];
        #pragma unroll
        for (int mt = 0; mt < 4; mt++)
            ldm_x4(af[mt], st + a_off + (uint32_t)(mt * 16 * SA * 2 + kk * 2));
        #pragma unroll
        for (int p = 0; p < 2; p++)
            ldm_x4(&bf[p * 4], st + b_off + (uint32_t)(p * 16 * SA * 2 + kk * 2));
        #pragma unroll
        for (int mt = 0; mt < 4; mt++)
            #pragma unroll
            for (int nt = 0; nt < 4; nt++)
                mma16816(acc[mt][nt], af[mt], &bf[nt * 2]);
    }
}

// ---------------------------------------------------------------------------
// Fused QKV GEMM: A = x fp32 converted in-kernel (half-stage interleave).
// Per iter c: CP_WAIT(0) -> sync -> load_B(c+1) -> ldgA half0 -> MMA -> 
//   stsA half0 + ldgA half1 -> (MMA continues) -> stsA half1.
// All slot-(c+1) writes follow the sync retiring mma(c-1)'s readers.
// ---------------------------------------------------------------------------
__global__ __launch_bounds__(NTHR, 2)
void gemm_qkv(const float* __restrict__ X, const __half* __restrict__ Wt,
              const float* __restrict__ bq, const float* __restrict__ bk,
              const float* __restrict__ bv,
              __half* __restrict__ Qo, __half* __restrict__ Ko,
              __half* __restrict__ Vo)
{
    extern __shared__ char smem[];
    const uint32_t sbase = smem_u32(smem);
    GEMM_LANE_SETUP();

    const int wsel = blockIdx.x >> 3;                 // 0,1,2 -> Wq,Wk,Wv
    const int n0   = (blockIdx.x & 7) * BN;
    const int r0   = blockIdx.y * BM;
    const __half* B = Wt + (size_t)wsel * DMODEL * DMODEL;
    const float* bias = (wsel == 0) ? bq : (wsel == 1) ? bk : bv;
    __half* C = (wsel == 0) ? Qo : (wsel == 1) ? Ko : Vo;
    const float osc = (wsel == 0) ? QSCALE : 1.0f;

    float acc[4][4][4];
    #pragma unroll
    for (int i = 0; i < 4; i++)
        #pragma unroll
        for (int j = 0; j < 4; j++)
            #pragma unroll
            for (int r = 0; r < 4; r++) acc[i][j][r] = 0.0f;

    // prologue: stage 0 (B async; A ldg+sts both halves)
    load_B(sbase, 0, tid, B, n0, 0);
    {
        float4 ar[4];
        ldgA_half(ar, X, r0, 0, tid, 0);
        stsA_half(smem, 0, ar, tid, 0);
        ldgA_half(ar, X, r0, 0, tid, 1);
        stsA_half(smem, 0, ar, tid, 1);
    }

    for (int c = 0; c < NSTAGE; c++) {
        CP_WAIT(0);            // stage c's B complete
        __syncthreads();       // readers of slot (c+1)&1 (mma c-1) done
        const bool more = (c + 1 < NSTAGE);
        if (more) load_B(sbase, (c + 1) & 1, tid, B, n0, (c + 1) * BK);

        const uint32_t st = sbase + (c & 1) * STAGE_B;
        float4 ar[4];
        if (more) ldgA_half(ar, X, r0, (c + 1) * BK, tid, 0);
        mma_stage(st, a_off, b_off, acc);
        if (more) {
            stsA_half(smem, (c + 1) & 1, ar, tid, 0);
            ldgA_half(ar, X, r0, (c + 1) * BK, tid, 1);
            stsA_half(smem, (c + 1) & 1, ar, tid, 1);
        }
    }

    #pragma unroll
    for (int mt = 0; mt < 4; mt++) {
        int row0 = r0 + wm * 64 + mt * 16 + g;
        #pragma unroll
        for (int nt = 0; nt < 4; nt++) {
            int col = n0 + wn * 32 + nt * 8 + tq * 2;
            float2 bvv = *(const float2*)&bias[col];
            *(uint32_t*)&C[(size_t)row0 * DMODEL + col] =
                packh2((acc[mt][nt][0] + bvv.x) * osc, (acc[mt][nt][1] + bvv.y) * osc);
            *(uint32_t*)&C[(size_t)(row0 + 8) * DMODEL + col] =
                packh2((acc[mt][nt][2] + bvv.x) * osc, (acc[mt][nt][3] + bvv.y) * osc);
        }
    }
}

// ---------------------------------------------------------------------------
// O-projection GEMM (fp32 accum, fp16 A via cp.async); race-free order.
// ---------------------------------------------------------------------------
__global__ __launch_bounds__(NTHR, 2)
void gemm_o(const __half* __restrict__ A, const __half* __restrict__ B,
            const float* __restrict__ bias, float* __restrict__ C)
{
    extern __shared__ char smem[];
    const uint32_t sbase = smem_u32(smem);
    GEMM_LANE_SETUP();

    const int r0 = blockIdx.y * BM;
    const int n0 = blockIdx.x * BN;

    float acc[4][4][4];
    #pragma unroll
    for (int i = 0; i < 4; i++)
        #pragma unroll
        for (int j = 0; j < 4; j++)
            #pragma unroll
            for (int r = 0; r < 4; r++) acc[i][j][r] = 0.0f;

    load_AB(sbase, 0, tid, A, B, r0, n0, 0);

    for (int c = 0; c < NSTAGE; c++) {
        CP_WAIT(0);
        __syncthreads();
        if (c + 1 < NSTAGE)
            load_AB(sbase, (c + 1) & 1, tid, A, B, r0, n0, (c + 1) * BK);
        mma_stage(sbase + (c & 1) * STAGE_B, a_off, b_off, acc);
    }

    #pragma unroll
    for (int mt = 0; mt < 4; mt++) {
        int row0 = r0 + wm * 64 + mt * 16 + g;
        #pragma unroll
        for (int nt = 0; nt < 4; nt++) {
            int col = n0 + wn * 32 + nt * 8 + tq * 2;
            float2 bvv = *(const float2*)&bias[col];
            *(float2*)&C[(size_t)row0 * DMODEL + col] =
                make_float2(acc[mt][nt][0] + bvv.x, acc[mt][nt][1] + bvv.y);
            *(float2*)&C[(size_t)(row0 + 8) * DMODEL + col] =
                make_float2(acc[mt][nt][2] + bvv.x, acc[mt][nt][3] + bvv.y);
        }
    }
}

// ---------------------------------------------------------------------------
// Tensor-core block-diagonal attention (unchanged from R13)
// ---------------------------------------------------------------------------
#define ASW(o) ((o) ^ (((o) >> 3) & 0x70))
#define AKV_B  (CHUNK * 128)
#define ATTN_SMEM (2 * AKV_B)          // 65536

__global__ __launch_bounds__(128, 3)
void attn_tc(const __half* __restrict__ Qg, const __half* __restrict__ Kg,
             const __half* __restrict__ Vg, __half* __restrict__ ctx)
{
    extern __shared__ char smc[];
    const uint32_t sbK = smem_u32(smc);
    const uint32_t sbV = sbK + AKV_B;

    const int gb = blockIdx.x >> 1, qh = blockIdx.x & 1;
    const int h = blockIdx.y, b = blockIdx.z;
    const int tid = threadIdx.x;
    const int rowBase  = b * SEQ + gb * CHUNK;
    const int qRowBase = rowBase + qh * 128;
    const int colBase  = h * HEADDIM;

    #pragma unroll
    for (int it = 0; it < 16; it++) {
        int u = tid + it * 128;
        int r = u >> 3, ch = u & 7;
        uint32_t so = ASW((uint32_t)(r * 128 + ch * 16));
        size_t go = (size_t)(rowBase + r) * DMODEL + colBase + ch * 8;
        CP_ASYNC16(sbK + so, Kg + go);
        CP_ASYNC16(sbV + so, Vg + go);
    }
    CP_COMMIT();

    const int wid  = tid >> 5;
    const int lane = tid & 31;
    const int g  = lane >> 2;
    const int tq = lane & 3;
    const int quad = lane >> 3;
    const int qr   = lane & 7;
    const int qrow0 = wid * 32;

    uint32_t qf[2][4][4];
    {
        const __half* Qp = Qg + (size_t)(qRowBase + qrow0) * DMODEL + colBase;
        #pragma unroll
        for (int mt = 0; mt < 2; mt++)
            #pragma unroll
            for (int ks = 0; ks < 4; ks++) {
                size_t base = (size_t)(mt * 16 + g) * DMODEL + ks * 16 + tq * 2;
                qf[mt][ks][0] = *(const uint32_t*)&Qp[base];
                qf[mt][ks][1] = *(const uint32_t*)&Qp[base + 8 * DMODEL];
                qf[mt][ks][2] = *(const uint32_t*)&Qp[base + 8];
                qf[mt][ks][3] = *(const uint32_t*)&Qp[base + 8 * DMODEL + 8];
            }
    }

    float o[2][8][4];
    float ol[2][4];
    #pragma unroll
    for (int mt = 0; mt < 2; mt++) {
        #pragma unroll
        for (int nt = 0; nt < 8; nt++)
            #pragma unroll
            for (int r = 0; r < 4; r++) o[mt][nt][r] = 0.0f;
        #pragma unroll
        for (int r = 0; r < 4; r++) ol[mt][r] = 0.0f;
    }
    const uint32_t onesf[2] = {0x3C003C00u, 0x3C003C00u};

    CP_WAIT(0);
    __syncthreads();

    for (int kt = 0; kt < 4; kt++) {
        float s[2][8][4];
        #pragma unroll
        for (int mt = 0; mt < 2; mt++)
            #pragma unroll
            for (int nt = 0; nt < 8; nt++)
                #pragma unroll
                for (int r = 0; r < 4; r++) s[mt][nt][r] = 0.0f;

        #pragma unroll
        for (int ks = 0; ks < 4; ks++) {
            #pragma unroll
            for (int np = 0; np < 4; np++) {
                uint32_t kf[4];
                uint32_t addr = sbK + ASW((uint32_t)(
                    (kt * 64 + np * 16 + (quad >> 1) * 8 + qr) * 128
                    + (quad & 1) * 16 + ks * 32));
                ldm_x4(kf, addr);
                #pragma unroll
                for (int mt = 0; mt < 2; mt++) {
                    mma16816(s[mt][2 * np],     qf[mt][ks], &kf[0]);
                    mma16816(s[mt][2 * np + 1], qf[mt][ks], &kf[2]);
                }
            }
        }

        uint32_t pf[2][4][4];
        #pragma unroll
        for (int mt = 0; mt < 2; mt++)
            #pragma unroll
            for (int ks = 0; ks < 4; ks++) {
                pf[mt][ks][0] = ex2h2(packh2(s[mt][2 * ks][0],     s[mt][2 * ks][1]));
                pf[mt][ks][1] = ex2h2(packh2(s[mt][2 * ks][2],     s[mt][2 * ks][3]));
                pf[mt][ks][2] = ex2h2(packh2(s[mt][2 * ks + 1][0], s[mt][2 * ks + 1][1]));
                pf[mt][ks][3] = ex2h2(packh2(s[mt][2 * ks + 1][2], s[mt][2 * ks + 1][3]));
            }

        #pragma unroll
        for (int ks = 0; ks < 4; ks++) {
            #pragma unroll
            for (int np = 0; np < 4; np++) {
                uint32_t vf[4];
                uint32_t addr = sbV + ASW((uint32_t)(
                    (kt * 64 + ks * 16 + (quad & 1) * 8 + qr) * 128
                    + np * 32 + (quad >> 1) * 16));
                ldm_x4_t(vf, addr);
                #pragma unroll
                for (int mt = 0; mt < 2; mt++) {
                    mma16816(o[mt][2 * np],     pf[mt][ks], &vf[0]);
                    mma16816(o[mt][2 * np + 1], pf[mt][ks], &vf[2]);
                }
            }
            #pragma unroll
            for (int mt = 0; mt < 2; mt++)
                mma16816(ol[mt], pf[mt][ks], onesf);
        }
    }

    #pragma unroll
    for (int mt = 0; mt < 2; mt++) {
        #pragma unroll
        for (int h2 = 0; h2 < 2; h2++) {
            float inv = 1.0f / ol[mt][2 * h2];
            int row = qRowBase + qrow0 + mt * 16 + h2 * 8 + g;
            #pragma unroll
            for (int nt = 0; nt < 8; nt++) {
                uint32_t v = packh2(o[mt][nt][2 * h2] * inv, o[mt][nt][2 * h2 + 1] * inv);
                *(uint32_t*)&ctx[(size_t)row * DMODEL + colBase + nt * 8 + tq * 2] = v;
            }
        }
    }
}

// ---------------------------------------------------------------------------
// Launch — 4 kernels total
// ---------------------------------------------------------------------------
extern "C" void kernel_launch(void* const* d_in, const int* in_sizes, int n_in,
                              void* d_out, int out_size)
{
    const float* x  = (const float*)d_in[0];
    const float* Wq = (const float*)d_in[1];
    const float* bq = (const float*)d_in[2];
    const float* Wk = (const float*)d_in[3];
    const float* bk = (const float*)d_in[4];
    const float* Wv = (const float*)d_in[5];
    const float* bv = (const float*)d_in[6];
    const float* Wo = (const float*)d_in[7];
    const float* bo = (const float*)d_in[8];
    float* out = (float*)d_out;

    __half *Qh, *Kh, *Vh, *Ch, *Wt;
    cudaGetSymbolAddress((void**)&Qh, g_Qh);
    cudaGetSymbolAddress((void**)&Kh, g_Kh);
    cudaGetSymbolAddress((void**)&Vh, g_Vh);
    cudaGetSymbolAddress((void**)&Ch, g_Ch);
    cudaGetSymbolAddress((void**)&Wt, g_Wt);
    const size_t WSZ = (size_t)DMODEL * DMODEL;

    cudaFuncSetAttribute(gemm_qkv,
                         cudaFuncAttributeMaxDynamicSharedMemorySize, GEMM_SMEM);
    cudaFuncSetAttribute(gemm_o,
                         cudaFuncAttributeMaxDynamicSharedMemorySize, GEMM_SMEM);
    cudaFuncSetAttribute(attn_tc,
                         cudaFuncAttributeMaxDynamicSharedMemorySize, ATTN_SMEM);

    wconv4<<<dim3(DMODEL / 32, DMODEL / 32, 4), 256>>>(Wq, Wk, Wv, Wo, Wt);

    // QKV: 3 weights x 8 n-blocks (x-fastest keeps same-row CTAs concurrent
    // for L2-shared A reads), 256 row-blocks
    gemm_qkv<<<dim3(24, MROWS / BM), NTHR, GEMM_SMEM>>>(
        x, Wt, bq, bk, bv, Qh, Kh, Vh);

    attn_tc<<<dim3(NBLKS * 2, NHEADS, BATCH), 128, ATTN_SMEM>>>(Qh, Kh, Vh, Ch);

    gemm_o<<<dim3(DMODEL / BN, MROWS / BM), NTHR, GEMM_SMEM>>>(
        Ch, Wt + 3 * WSZ, bo, out);
}

// round 17
// speedup vs baseline: 1.1188x; 1.0135x over previous
#include <cuda_runtime.h>
#include <cuda_fp16.h>
#include <math.h>
#include <cstdint>

// Problem constants
#define BATCH   4
#define SEQ     8192
#define DMODEL  1024
#define NHEADS  16
#define HEADDIM 64
#define CHUNK   256
#define NBLKS   (SEQ / CHUNK)        // 32
#define MROWS   (BATCH * SEQ)        // 32768

// ---------------------------------------------------------------------------
// Scratch (device globals — no runtime allocation allowed)
// ---------------------------------------------------------------------------
__device__ __half g_Qh[(size_t)MROWS * DMODEL];      // Q fp16 (pre-scaled by log2e/32)
__device__ __half g_Kh[(size_t)MROWS * DMODEL];      // K fp16
__device__ __half g_Vh[(size_t)MROWS * DMODEL];      // V fp16
__device__ __half g_Ch[(size_t)MROWS * DMODEL];      // ctx fp16
__device__ __half g_Wt[4][(size_t)DMODEL * DMODEL];  // W^T fp16 (K-major)

// ---------------------------------------------------------------------------
// PTX helpers (baseline sm_80 features only)
// ---------------------------------------------------------------------------
__device__ __forceinline__ uint32_t smem_u32(const void* p) {
    uint32_t a;
    asm("{ .reg .u64 t; cvta.to.shared.u64 t, %1; cvt.u32.u64 %0, t; }"
        : "=r"(a) : "l"(p));
    return a;
}
#define CP_ASYNC16(dst, src) \
    asm volatile("cp.async.cg.shared.global [%0], [%1], 16;" \
                 :: "r"(dst), "l"(src))
#define CP_COMMIT() asm volatile("cp.async.commit_group;" ::: "memory")
#define CP_WAIT(n)  asm volatile("cp.async.wait_group %0;" :: "n"(n) : "memory")

__device__ __forceinline__ void mma16816(float* c, const uint32_t* a, const uint32_t* b) {
    asm volatile(
        "mma.sync.aligned.m16n8k16.row.col.f32.f16.f16.f32 "
        "{%0,%1,%2,%3}, {%4,%5,%6,%7}, {%8,%9}, {%0,%1,%2,%3};"
        : "+f"(c[0]), "+f"(c[1]), "+f"(c[2]), "+f"(c[3])
        : "r"(a[0]), "r"(a[1]), "r"(a[2]), "r"(a[3]), "r"(b[0]), "r"(b[1]));
}
__device__ __forceinline__ void ldm_x4(uint32_t* r, uint32_t addr) {
    asm volatile("ldmatrix.sync.aligned.m8n8.x4.shared.b16 {%0,%1,%2,%3}, [%4];"
                 : "=r"(r[0]), "=r"(r[1]), "=r"(r[2]), "=r"(r[3]) : "r"(addr));
}
__device__ __forceinline__ void ldm_x4_t(uint32_t* r, uint32_t addr) {
    asm volatile("ldmatrix.sync.aligned.m8n8.x4.trans.shared.b16 {%0,%1,%2,%3}, [%4];"
                 : "=r"(r[0]), "=r"(r[1]), "=r"(r[2]), "=r"(r[3]) : "r"(addr));
}
__device__ __forceinline__ uint32_t packh2(float a, float b) {
    __half2 h = __floats2half2_rn(a, b);
    return *(uint32_t*)&h;
}
__device__ __forceinline__ uint32_t ex2h2(uint32_t a) {
    uint32_t d;
    asm("ex2.approx.f16x2 %0, %1;" : "=r"(d) : "r"(a));
    return d;
}

// ---------------------------------------------------------------------------
// Fused weight transpose+convert (4 weights, one launch)
// ---------------------------------------------------------------------------
__global__ __launch_bounds__(256)
void wconv4(const float* __restrict__ W0, const float* __restrict__ W1,
            const float* __restrict__ W2, const float* __restrict__ W3,
            __half* __restrict__ T)
{
    __shared__ float t[32][33];
    const int z = blockIdx.z;
    const float* W = (z == 0) ? W0 : (z == 1) ? W1 : (z == 2) ? W2 : W3;
    __half* To = T + (size_t)z * DMODEL * DMODEL;
    const int n0 = blockIdx.x * 32, k0 = blockIdx.y * 32;
    const int tx = threadIdx.x & 31, ty = threadIdx.x >> 5;
    #pragma unroll
    for (int i = 0; i < 4; i++) {
        int k = k0 + ty + i * 8;
        t[ty + i * 8][tx] = W[(size_t)k * DMODEL + n0 + tx];
    }
    __syncthreads();
    #pragma unroll
    for (int i = 0; i < 4; i++) {
        int n = n0 + ty + i * 8;
        To[(size_t)n * DMODEL + k0 + tx] = __float2half(t[tx][ty + i * 8]);
    }
}

// ---------------------------------------------------------------------------
// Shared GEMM constants: BK=64, 72-half padded rows, warp tile 64x32,
// fp32 accum, NPIPE=2, race-free order (wait -> sync -> load -> mma).
// ---------------------------------------------------------------------------
#define BK 64
#define SA 72
#define TILE_A  (128 * SA * 2)        // 18432 (BM=128 both kernels)
#define NSTAGE (DMODEL / BK)          // 16
#define QSCALE 0.04508422f            // log2(e)/32

// MMA core over one BK=64 stage (shared; offsets encode per-kernel bases)
__device__ __forceinline__ void mma_stage(uint32_t st, uint32_t a_off, uint32_t b_off,
                                          float acc[4][4][4])
{
    #pragma unroll
    for (int kk = 0; kk < BK; kk += 16) {
        uint32_t af[4][4], bf[8];
        #pragma unroll
        for (int mt = 0; mt < 4; mt++)
            ldm_x4(af[mt], st + a_off + (uint32_t)(mt * 16 * SA * 2 + kk * 2));
        #pragma unroll
        for (int p = 0; p < 2; p++)
            ldm_x4(&bf[p * 4], st + b_off + (uint32_t)(p * 16 * SA * 2 + kk * 2));
        #pragma unroll
        for (int mt = 0; mt < 4; mt++)
            #pragma unroll
            for (int nt = 0; nt < 4; nt++)
                mma16816(acc[mt][nt], af[mt], &bf[nt * 2]);
    }
}

// ===========================================================================
// QKV GEMM — R13 config: CTA 128x256, 512 thr / 16 warps (2x8), 1 CTA/SM.
// A = x fp32 converted in-kernel.
// ===========================================================================
#define QNTHR 512
#define QBN   256
#define QTILE_B (QBN * SA * 2)          // 36864
#define QOFF_B  TILE_A
#define QSTAGE  (TILE_A + QTILE_B)      // 55296
#define QSMEM   (2 * QSTAGE)            // 110592

__device__ __forceinline__ void q_load_B(
    uint32_t sbase, int slot, int tid,
    const __half* __restrict__ B, int n0, int k0)
{
    const uint32_t st = sbase + slot * QSTAGE + QOFF_B;
    #pragma unroll
    for (int it = 0; it < 4; it++) {          // 256 rows x 8 chunks / 512
        int u = tid + it * QNTHR;
        int row = u >> 3, ch = u & 7;
        CP_ASYNC16(st + (uint32_t)(row * SA * 2 + ch * 16),
                   B + (size_t)(n0 + row) * DMODEL + k0 + ch * 8);
    }
    CP_COMMIT();
}
__device__ __forceinline__ void q_ldgA(float4* r, const float* __restrict__ X,
                                       int r0, int k0, int tid)
{
    #pragma unroll
    for (int it = 0; it < 4; it++) {          // 128 rows x 16 float4 / 512
        int u = tid + it * QNTHR;
        int row = u >> 4, ch = u & 15;
        r[it] = *(const float4*)&X[(size_t)(r0 + row) * DMODEL + k0 + ch * 4];
    }
}
__device__ __forceinline__ void q_stsA(char* smem, int slot, const float4* r, int tid)
{
    char* st = smem + slot * QSTAGE;
    #pragma unroll
    for (int it = 0; it < 4; it++) {
        int u = tid + it * QNTHR;
        int row = u >> 4, ch = u & 15;
        uint2 v;
        v.x = packh2(r[it].x, r[it].y);
        v.y = packh2(r[it].z, r[it].w);
        *(uint2*)(st + row * (SA * 2) + ch * 8) = v;
    }
}

__global__ __launch_bounds__(QNTHR, 1)
void gemm_qkv(const float* __restrict__ X, const __half* __restrict__ Wt,
              const float* __restrict__ bq, const float* __restrict__ bk,
              const float* __restrict__ bv,
              __half* __restrict__ Qo, __half* __restrict__ Ko,
              __half* __restrict__ Vo)
{
    extern __shared__ char smem[];
    const uint32_t sbase = smem_u32(smem);
    const int tid  = threadIdx.x;
    const int wid  = tid >> 5;
    const int lane = tid & 31;
    const int wm = wid & 1;              // 0..1 : 64-row slab
    const int wn = wid >> 1;             // 0..7 : 32-col slab
    const int g  = lane >> 2;
    const int tq = lane & 3;
    const int quad = lane >> 3;
    const int qr   = lane & 7;
    const uint32_t a_off = (uint32_t)((wm * 64 + (quad & 1) * 8 + qr) * SA * 2
                                      + (quad >> 1) * 16);
    const uint32_t b_off = (uint32_t)QOFF_B
                         + (uint32_t)((wn * 32 + (quad >> 1) * 8 + qr) * SA * 2
                                      + (quad & 1) * 16);

    const int wsel = blockIdx.x >> 2;
    const int n0   = (blockIdx.x & 3) * QBN;
    const int r0   = blockIdx.y * 128;
    const __half* B = Wt + (size_t)wsel * DMODEL * DMODEL;
    const float* bias = (wsel == 0) ? bq : (wsel == 1) ? bk : bv;
    __half* C = (wsel == 0) ? Qo : (wsel == 1) ? Ko : Vo;
    const float osc = (wsel == 0) ? QSCALE : 1.0f;

    float acc[4][4][4];
    #pragma unroll
    for (int i = 0; i < 4; i++)
        #pragma unroll
        for (int j = 0; j < 4; j++)
            #pragma unroll
            for (int r = 0; r < 4; r++) acc[i][j][r] = 0.0f;

    // prologue
    q_load_B(sbase, 0, tid, B, n0, 0);
    {
        float4 ar[4];
        q_ldgA(ar, X, r0, 0, tid);
        q_stsA(smem, 0, ar, tid);
    }

    for (int c = 0; c < NSTAGE; c++) {
        CP_WAIT(0);            // stage c's B complete
        __syncthreads();       // readers of slot (c+1)&1 (mma c-1) done
        if (c + 1 < NSTAGE)
            q_load_B(sbase, (c + 1) & 1, tid, B, n0, (c + 1) * BK);

        float4 ar[4];
        if (c + 1 < NSTAGE) q_ldgA(ar, X, r0, (c + 1) * BK, tid);

        mma_stage(sbase + (c & 1) * QSTAGE, a_off, b_off, acc);

        if (c + 1 < NSTAGE) q_stsA(smem, (c + 1) & 1, ar, tid);
    }

    #pragma unroll
    for (int mt = 0; mt < 4; mt++) {
        int row0 = r0 + wm * 64 + mt * 16 + g;
        #pragma unroll
        for (int nt = 0; nt < 4; nt++) {
            int col = n0 + wn * 32 + nt * 8 + tq * 2;
            float2 bvv = *(const float2*)&bias[col];
            *(uint32_t*)&C[(size_t)row0 * DMODEL + col] =
                packh2((acc[mt][nt][0] + bvv.x) * osc, (acc[mt][nt][1] + bvv.y) * osc);
            *(uint32_t*)&C[(size_t)(row0 + 8) * DMODEL + col] =
                packh2((acc[mt][nt][2] + bvv.x) * osc, (acc[mt][nt][3] + bvv.y) * osc);
        }
    }
}

// ===========================================================================
// O-projection GEMM — R16 config: CTA 128x128, 256 thr / 8 warps (2x4),
// 2 CTAs/SM (independent barrier domains cover each other's bubbles).
// ===========================================================================
#define ONTHR 256
#define OBN   128
#define OTILE_B (OBN * SA * 2)          // 18432
#define OOFF_B  TILE_A
#define OSTAGE  (TILE_A + OTILE_B)      // 36864
#define OSMEM   (2 * OSTAGE)            // 73728

__device__ __forceinline__ void o_load_AB(
    uint32_t sbase, int slot, int tid,
    const __half* __restrict__ A, const __half* __restrict__ B,
    int r0, int n0, int k0)
{
    const uint32_t st = sbase + slot * OSTAGE;
    #pragma unroll
    for (int it = 0; it < 4; it++) {          // A: 128 rows x 8 chunks / 256
        int u = tid + it * ONTHR;
        int row = u >> 3, ch = u & 7;
        CP_ASYNC16(st + (uint32_t)(row * SA * 2 + ch * 16),
                   A + (size_t)(r0 + row) * DMODEL + k0 + ch * 8);
    }
    #pragma unroll
    for (int it = 0; it < 4; it++) {          // B: 128 rows x 8 chunks / 256
        int u = tid + it * ONTHR;
        int row = u >> 3, ch = u & 7;
        CP_ASYNC16(st + OOFF_B + (uint32_t)(row * SA * 2 + ch * 16),
                   B + (size_t)(n0 + row) * DMODEL + k0 + ch * 8);
    }
    CP_COMMIT();
}

__global__ __launch_bounds__(ONTHR, 2)
void gemm_o(const __half* __restrict__ A, const __half* __restrict__ B,
            const float* __restrict__ bias, float* __restrict__ C)
{
    extern __shared__ char smem[];
    const uint32_t sbase = smem_u32(smem);
    const int tid  = threadIdx.x;
    const int wid  = tid >> 5;
    const int lane = tid & 31;
    const int wm = wid & 1;              // 0..1
    const int wn = wid >> 1;             // 0..3
    const int g  = lane >> 2;
    const int tq = lane & 3;
    const int quad = lane >> 3;
    const int qr   = lane & 7;
    const uint32_t a_off = (uint32_t)((wm * 64 + (quad & 1) * 8 + qr) * SA * 2
                                      + (quad >> 1) * 16);
    const uint32_t b_off = (uint32_t)OOFF_B
                         + (uint32_t)((wn * 32 + (quad >> 1) * 8 + qr) * SA * 2
                                      + (quad & 1) * 16);

    const int r0 = blockIdx.y * 128;
    const int n0 = blockIdx.x * OBN;

    float acc[4][4][4];
    #pragma unroll
    for (int i = 0; i < 4; i++)
        #pragma unroll
        for (int j = 0; j < 4; j++)
            #pragma unroll
            for (int r = 0; r < 4; r++) acc[i][j][r] = 0.0f;

    o_load_AB(sbase, 0, tid, A, B, r0, n0, 0);

    for (int c = 0; c < NSTAGE; c++) {
        CP_WAIT(0);
        __syncthreads();
        if (c + 1 < NSTAGE)
            o_load_AB(sbase, (c + 1) & 1, tid, A, B, r0, n0, (c + 1) * BK);
        mma_stage(sbase + (c & 1) * OSTAGE, a_off, b_off, acc);
    }

    #pragma unroll
    for (int mt = 0; mt < 4; mt++) {
        int row0 = r0 + wm * 64 + mt * 16 + g;
        #pragma unroll
        for (int nt = 0; nt < 4; nt++) {
            int col = n0 + wn * 32 + nt * 8 + tq * 2;
            float2 bvv = *(const float2*)&bias[col];
            *(float2*)&C[(size_t)row0 * DMODEL + col] =
                make_float2(acc[mt][nt][0] + bvv.x, acc[mt][nt][1] + bvv.y);
            *(float2*)&C[(size_t)(row0 + 8) * DMODEL + col] =
                make_float2(acc[mt][nt][2] + bvv.x, acc[mt][nt][3] + bvv.y);
        }
    }
}

// ---------------------------------------------------------------------------
// Tensor-core block-diagonal attention (unchanged from R13)
// ---------------------------------------------------------------------------
#define ASW(o) ((o) ^ (((o) >> 3) & 0x70))
#define AKV_B  (CHUNK * 128)
#define ATTN_SMEM (2 * AKV_B)          // 65536

__global__ __launch_bounds__(128, 3)
void attn_tc(const __half* __restrict__ Qg, const __half* __restrict__ Kg,
             const __half* __restrict__ Vg, __half* __restrict__ ctx)
{
    extern __shared__ char smc[];
    const uint32_t sbK = smem_u32(smc);
    const uint32_t sbV = sbK + AKV_B;

    const int gb = blockIdx.x >> 1, qh = blockIdx.x & 1;
    const int h = blockIdx.y, b = blockIdx.z;
    const int tid = threadIdx.x;
    const int rowBase  = b * SEQ + gb * CHUNK;
    const int qRowBase = rowBase + qh * 128;
    const int colBase  = h * HEADDIM;

    #pragma unroll
    for (int it = 0; it < 16; it++) {
        int u = tid + it * 128;
        int r = u >> 3, ch = u & 7;
        uint32_t so = ASW((uint32_t)(r * 128 + ch * 16));
        size_t go = (size_t)(rowBase + r) * DMODEL + colBase + ch * 8;
        CP_ASYNC16(sbK + so, Kg + go);
        CP_ASYNC16(sbV + so, Vg + go);
    }
    CP_COMMIT();

    const int wid  = tid >> 5;
    const int lane = tid & 31;
    const int g  = lane >> 2;
    const int tq = lane & 3;
    const int quad = lane >> 3;
    const int qr   = lane & 7;
    const int qrow0 = wid * 32;

    uint32_t qf[2][4][4];
    {
        const __half* Qp = Qg + (size_t)(qRowBase + qrow0) * DMODEL + colBase;
        #pragma unroll
        for (int mt = 0; mt < 2; mt++)
            #pragma unroll
            for (int ks = 0; ks < 4; ks++) {
                size_t base = (size_t)(mt * 16 + g) * DMODEL + ks * 16 + tq * 2;
                qf[mt][ks][0] = *(const uint32_t*)&Qp[base];
                qf[mt][ks][1] = *(const uint32_t*)&Qp[base + 8 * DMODEL];
                qf[mt][ks][2] = *(const uint32_t*)&Qp[base + 8];
                qf[mt][ks][3] = *(const uint32_t*)&Qp[base + 8 * DMODEL + 8];
            }
    }

    float o[2][8][4];
    float ol[2][4];
    #pragma unroll
    for (int mt = 0; mt < 2; mt++) {
        #pragma unroll
        for (int nt = 0; nt < 8; nt++)
            #pragma unroll
            for (int r = 0; r < 4; r++) o[mt][nt][r] = 0.0f;
        #pragma unroll
        for (int r = 0; r < 4; r++) ol[mt][r] = 0.0f;
    }
    const uint32_t onesf[2] = {0x3C003C00u, 0x3C003C00u};

    CP_WAIT(0);
    __syncthreads();

    for (int kt = 0; kt < 4; kt++) {
        float s[2][8][4];
        #pragma unroll
        for (int mt = 0; mt < 2; mt++)
            #pragma unroll
            for (int nt = 0; nt < 8; nt++)
                #pragma unroll
                for (int r = 0; r < 4; r++) s[mt][nt][r] = 0.0f;

        #pragma unroll
        for (int ks = 0; ks < 4; ks++) {
            #pragma unroll
            for (int np = 0; np < 4; np++) {
                uint32_t kf[4];
                uint32_t addr = sbK + ASW((uint32_t)(
                    (kt * 64 + np * 16 + (quad >> 1) * 8 + qr) * 128
                    + (quad & 1) * 16 + ks * 32));
                ldm_x4(kf, addr);
                #pragma unroll
                for (int mt = 0; mt < 2; mt++) {
                    mma16816(s[mt][2 * np],     qf[mt][ks], &kf[0]);
                    mma16816(s[mt][2 * np + 1], qf[mt][ks], &kf[2]);
                }
            }
        }

        uint32_t pf[2][4][4];
        #pragma unroll
        for (int mt = 0; mt < 2; mt++)
            #pragma unroll
            for (int ks = 0; ks < 4; ks++) {
                pf[mt][ks][0] = ex2h2(packh2(s[mt][2 * ks][0],     s[mt][2 * ks][1]));
                pf[mt][ks][1] = ex2h2(packh2(s[mt][2 * ks][2],     s[mt][2 * ks][3]));
                pf[mt][ks][2] = ex2h2(packh2(s[mt][2 * ks + 1][0], s[mt][2 * ks + 1][1]));
                pf[mt][ks][3] = ex2h2(packh2(s[mt][2 * ks + 1][2], s[mt][2 * ks + 1][3]));
            }

        #pragma unroll
        for (int ks = 0; ks < 4; ks++) {
            #pragma unroll
            for (int np = 0; np < 4; np++) {
                uint32_t vf[4];
                uint32_t addr = sbV + ASW((uint32_t)(
                    (kt * 64 + ks * 16 + (quad & 1) * 8 + qr) * 128
                    + np * 32 + (quad >> 1) * 16));
                ldm_x4_t(vf, addr);
                #pragma unroll
                for (int mt = 0; mt < 2; mt++) {
                    mma16816(o[mt][2 * np],     pf[mt][ks], &vf[0]);
                    mma16816(o[mt][2 * np + 1], pf[mt][ks], &vf[2]);
                }
            }
            #pragma unroll
            for (int mt = 0; mt < 2; mt++)
                mma16816(ol[mt], pf[mt][ks], onesf);
        }
    }

    #pragma unroll
    for (int mt = 0; mt < 2; mt++) {
        #pragma unroll
        for (int h2 = 0; h2 < 2; h2++) {
            float inv = 1.0f / ol[mt][2 * h2];
            int row = qRowBase + qrow0 + mt * 16 + h2 * 8 + g;
            #pragma unroll
            for (int nt = 0; nt < 8; nt++) {
                uint32_t v = packh2(o[mt][nt][2 * h2] * inv, o[mt][nt][2 * h2 + 1] * inv);
                *(uint32_t*)&ctx[(size_t)row * DMODEL + colBase + nt * 8 + tq * 2] = v;
            }
        }
    }
}

// ---------------------------------------------------------------------------
// Launch — 4 kernels total
// ---------------------------------------------------------------------------
extern "C" void kernel_launch(void* const* d_in, const int* in_sizes, int n_in,
                              void* d_out, int out_size)
{
    const float* x  = (const float*)d_in[0];
    const float* Wq = (const float*)d_in[1];
    const float* bq = (const float*)d_in[2];
    const float* Wk = (const float*)d_in[3];
    const float* bk = (const float*)d_in[4];
    const float* Wv = (const float*)d_in[5];
    const float* bv = (const float*)d_in[6];
    const float* Wo = (const float*)d_in[7];
    const float* bo = (const float*)d_in[8];
    float* out = (float*)d_out;

    __half *Qh, *Kh, *Vh, *Ch, *Wt;
    cudaGetSymbolAddress((void**)&Qh, g_Qh);
    cudaGetSymbolAddress((void**)&Kh, g_Kh);
    cudaGetSymbolAddress((void**)&Vh, g_Vh);
    cudaGetSymbolAddress((void**)&Ch, g_Ch);
    cudaGetSymbolAddress((void**)&Wt, g_Wt);
    const size_t WSZ = (size_t)DMODEL * DMODEL;

    cudaFuncSetAttribute(gemm_qkv,
                         cudaFuncAttributeMaxDynamicSharedMemorySize, QSMEM);
    cudaFuncSetAttribute(gemm_o,
                         cudaFuncAttributeMaxDynamicSharedMemorySize, OSMEM);
    cudaFuncSetAttribute(attn_tc,
                         cudaFuncAttributeMaxDynamicSharedMemorySize, ATTN_SMEM);

    wconv4<<<dim3(DMODEL / 32, DMODEL / 32, 4), 256>>>(Wq, Wk, Wv, Wo, Wt);

    // QKV: 3 weights x 4 n-blocks of 256 (minimal B re-reads), 256 row-blocks
    gemm_qkv<<<dim3(12, MROWS / 128), QNTHR, QSMEM>>>(
        x, Wt, bq, bk, bv, Qh, Kh, Vh);

    attn_tc<<<dim3(NBLKS * 2, NHEADS, BATCH), 128, ATTN_SMEM>>>(Qh, Kh, Vh, Ch);

    // O-projection: 8 n-blocks of 128, 2 CTAs/SM
    gemm_o<<<dim3(DMODEL / OBN, MROWS / 128), ONTHR, OSMEM>>>(
        Ch, Wt + 3 * WSZ, bo, out);
}